// round 2
// baseline (speedup 1.0000x reference)
#include <cuda_runtime.h>

// Problem constants (fixed shapes from reference)
#define K_CODES 1024
#define C_DIM   256
#define HW      4096          // 64*64
#define BATCH   32
#define NPIX    (BATCH*HW)          // 131072 pixels
#define QN      (BATCH*C_DIM*HW)    // 8388608 quantized elements

// Tiling for the distance GEMM
#define TN 128   // pixels per block
#define TK 128   // codes per k-tile
#define CK 16    // C chunk

// Scratch (no cudaMalloc allowed)
__device__ float g_enorm[K_CODES];
__device__ float g_xnorm[NPIX];
__device__ int   g_idx[NPIX];

// ---------------------------------------------------------------------------
// 1) codebook row norms |e_k|^2. (Summation order irrelevant: enorm/ulp(256)
//    boundary distances are ~4e-6 while order-noise is ~1e-11.)
// ---------------------------------------------------------------------------
__global__ void enorm_kernel(const float* __restrict__ cb) {
    int k = blockIdx.x * blockDim.x + threadIdx.x;
    if (k < K_CODES) {
        const float4* row = reinterpret_cast<const float4*>(cb + (size_t)k * C_DIM);
        float s = 0.f;
        #pragma unroll
        for (int i = 0; i < C_DIM / 4; i++) {
            float4 v = row[i];
            s += v.x*v.x + v.y*v.y + v.z*v.z + v.w*v.w;
        }
        g_enorm[k] = s;
    }
}

// ---------------------------------------------------------------------------
// 1b) pixel norms |x_p|^2 = sum(x*x): square (rounded), then add — matches
//     jnp.sum(xf*xf). Exact value only matters through its binade; any
//     accurate fp32 order works. Coalesced: consecutive threads = consecutive hw.
// ---------------------------------------------------------------------------
__global__ void xnorm_kernel(const float* __restrict__ x) {
    int p = blockIdx.x * blockDim.x + threadIdx.x;
    if (p >= NPIX) return;
    int b  = p >> 12;
    int hw = p & (HW - 1);
    const float* xb = x + (size_t)b * C_DIM * HW + hw;
    float s = 0.f;
    #pragma unroll 8
    for (int c = 0; c < C_DIM; c++) {
        float v = xb[(size_t)c * HW];
        s = __fadd_rn(s, __fmul_rn(v, v));
    }
    g_xnorm[p] = s;
}

// ---------------------------------------------------------------------------
// 2) distance GEMM + argmin, emulating the reference's fp32 rounding:
//    s = fl( fl(xnorm_p + enorm_k) - fl(2*dot_pk) ), dot accumulated as a
//    single sequential FMA chain over c ascending (Eigen / cublas order).
//    argmin over k with lowest-k tie-break via packed (orderable_s, k) atomicMin.
// ---------------------------------------------------------------------------
__global__ __launch_bounds__(256, 2)
void argmin_kernel(const float* __restrict__ x, const float* __restrict__ cb) {
    __shared__ float Es[CK][TK + 4];   // [c][code], padded
    __shared__ float Xs[CK][TN + 4];   // [c][pixel], padded
    __shared__ unsigned long long best[TN];
    __shared__ float enorm_s[TK];
    __shared__ float xnorm_s[TN];

    const int tid = threadIdx.x;
    const int tx  = tid & 15;   // pixel group (8 pixels)
    const int ty  = tid >> 4;   // code group  (8 codes)
    const int p0  = blockIdx.x * TN;     // global pixel base
    const int b   = p0 >> 12;            // / 4096
    const int hw0 = p0 & (HW - 1);

    const float* xb = x + (size_t)b * C_DIM * HW;

    for (int i = tid; i < TN; i += 256) best[i] = 0xFFFFFFFFFFFFFFFFULL;
    if (tid < TN) xnorm_s[tid] = g_xnorm[p0 + tid];

    for (int kt = 0; kt < K_CODES; kt += TK) {
        if (tid < TK) enorm_s[tid] = g_enorm[kt + tid];

        float acc[8][8];
        #pragma unroll
        for (int i = 0; i < 8; i++)
            #pragma unroll
            for (int j = 0; j < 8; j++) acc[i][j] = 0.f;

        for (int ct = 0; ct < C_DIM; ct += CK) {
            __syncthreads();
            // E tile: 128 codes x 16 c, transposed into Es[c][code].
            #pragma unroll
            for (int l = 0; l < 2; l++) {
                int f  = tid + l * 256;          // 0..511
                int kk = f >> 2;                 // code row
                int c4 = f & 3;                  // float4 within the 16-c chunk
                float4 v = *reinterpret_cast<const float4*>(
                    cb + (size_t)(kt + kk) * C_DIM + ct + c4 * 4);
                Es[c4 * 4 + 0][kk] = v.x;
                Es[c4 * 4 + 1][kk] = v.y;
                Es[c4 * 4 + 2][kk] = v.z;
                Es[c4 * 4 + 3][kk] = v.w;
            }
            // X tile: 16 c x 128 pixels, coalesced along pixels.
            #pragma unroll
            for (int l = 0; l < 2; l++) {
                int f  = tid + l * 256;
                int cc = f >> 5;                 // 0..15
                int p4 = f & 31;
                float4 v = *reinterpret_cast<const float4*>(
                    xb + (size_t)(ct + cc) * HW + hw0 + p4 * 4);
                *reinterpret_cast<float4*>(&Xs[cc][p4 * 4]) = v;
            }
            __syncthreads();

            // Sequential FMA chain over c ascending — matches the reference
            // backend's per-element accumulation order/rounding.
            #pragma unroll
            for (int cc = 0; cc < CK; cc++) {
                float a[8], bv[8];
                #pragma unroll
                for (int i = 0; i < 8; i++) a[i]  = Es[cc][ty * 8 + i];
                #pragma unroll
                for (int j = 0; j < 8; j++) bv[j] = Xs[cc][tx * 8 + j];
                #pragma unroll
                for (int i = 0; i < 8; i++)
                    #pragma unroll
                    for (int j = 0; j < 8; j++)
                        acc[i][j] = __fmaf_rn(a[i], bv[j], acc[i][j]);
            }
        }

        // Scores with the reference's exact fp32 op sequence + argmin.
        #pragma unroll
        for (int j = 0; j < 8; j++) {
            int p = tx * 8 + j;
            float xn = xnorm_s[p];
            float bscore = 3.402823466e38f;
            int   bk = 0;
            #pragma unroll
            for (int i = 0; i < 8; i++) {
                float t = __fadd_rn(xn, enorm_s[ty * 8 + i]);        // fl(a+b)
                float s = __fsub_rn(t, __fmul_rn(2.0f, acc[i][j]));  // fl(.. - 2m)
                if (s < bscore) { bscore = s; bk = kt + ty * 8 + i; } // lowest k on tie
            }
            unsigned u = __float_as_uint(bscore);
            u = (u & 0x80000000u) ? ~u : (u | 0x80000000u);   // orderable transform
            unsigned long long key = ((unsigned long long)u << 32) | (unsigned)bk;
            atomicMin(&best[p], key);
        }
        __syncthreads();
    }

    for (int i = tid; i < TN; i += 256)
        g_idx[p0 + i] = (int)(best[i] & 0xFFFFFFFFu);
}

// ---------------------------------------------------------------------------
// 3) gather quantized output, (B,C,H,W) layout. Coalesced writes along hw;
//    codebook (1 MB) stays L2-resident for the scattered reads.
// ---------------------------------------------------------------------------
__global__ void gather_kernel(const float* __restrict__ cb, float* __restrict__ q) {
    long long o = (long long)blockIdx.x * blockDim.x + threadIdx.x;
    if (o >= (long long)QN) return;
    int hw = (int)(o & (HW - 1));
    long long t = o >> 12;            // b*256 + c
    int c = (int)(t & (C_DIM - 1));
    int b = (int)(t >> 8);
    int k = g_idx[b * HW + hw];
    q[o] = __ldg(cb + (size_t)k * C_DIM + c);
}

__global__ void idxf_kernel(float* __restrict__ out) {
    int n = blockIdx.x * blockDim.x + threadIdx.x;
    if (n < NPIX) out[n] = (float)g_idx[n];
}

__global__ void idxi_kernel(int* __restrict__ out) {
    int n = blockIdx.x * blockDim.x + threadIdx.x;
    if (n < NPIX) out[n] = g_idx[n];
}

// ---------------------------------------------------------------------------
extern "C" void kernel_launch(void* const* d_in, const int* in_sizes, int n_in,
                              void* d_out, int out_size) {
    const float* x  = (const float*)d_in[0];   // (32,256,64,64) f32
    const float* cb = (const float*)d_in[1];   // (1024,256) f32

    enorm_kernel<<<(K_CODES + 255) / 256, 256>>>(cb);
    xnorm_kernel<<<NPIX / 256, 256>>>(x);
    argmin_kernel<<<NPIX / TN, 256>>>(x, cb);

    if (out_size >= NPIX + QN) {
        // concatenated [indices (as f32), quantized]
        idxf_kernel<<<NPIX / 256, 256>>>((float*)d_out);
        gather_kernel<<<QN / 256, 256>>>(cb, (float*)d_out + NPIX);
    } else if (out_size >= QN) {
        gather_kernel<<<QN / 256, 256>>>(cb, (float*)d_out);
    } else if (out_size >= NPIX) {
        idxi_kernel<<<NPIX / 256, 256>>>((int*)d_out);
    }
}

// round 6
// speedup vs baseline: 1.1999x; 1.1999x over previous
#include <cuda_runtime.h>
#include <cuda_bf16.h>
#include <cstdint>

// ---------------------------------------------------------------------------
// Problem constants
// ---------------------------------------------------------------------------
#define K_CODES 1024
#define C_DIM   256
#define HW      4096
#define BATCH   32
#define NPIX    (BATCH*HW)          // 131072
#define QN      (BATCH*C_DIM*HW)    // 8388608

#define TNPIX   64                  // pixels per CTA
#define MARGIN  4e-3f
#define CAND_CAP 3072

// Scratch (device globals; no cudaMalloc allowed)
__device__ float g_enorm[K_CODES];
__device__ int   g_idx[NPIX];
__device__ __nv_bfloat16 g_cbhi[K_CODES * C_DIM];

// ---------------------------------------------------------------------------
// Warp MMA helpers — plain PTX features only (work on compute_103 target)
// ---------------------------------------------------------------------------
__device__ __forceinline__ uint32_t smem_u32(const void* p) {
    uint32_t a;
    asm("{ .reg .u64 t; cvta.to.shared.u64 t, %1; cvt.u32.u64 %0, t; }" : "=r"(a) : "l"(p));
    return a;
}
#define LDSM_X4(r, a) \
    asm volatile("ldmatrix.sync.aligned.m8n8.x4.shared.b16 {%0,%1,%2,%3}, [%4];" \
        : "=r"((r)[0]), "=r"((r)[1]), "=r"((r)[2]), "=r"((r)[3]) : "r"(a))
#define LDSM_X4_T(r, a) \
    asm volatile("ldmatrix.sync.aligned.m8n8.x4.trans.shared.b16 {%0,%1,%2,%3}, [%4];" \
        : "=r"((r)[0]), "=r"((r)[1]), "=r"((r)[2]), "=r"((r)[3]) : "r"(a))
#define MMA_BF16(d, a, b0, b1) \
    asm volatile("mma.sync.aligned.m16n8k16.row.col.f32.bf16.bf16.f32 " \
        "{%0,%1,%2,%3}, {%4,%5,%6,%7}, {%8,%9}, {%0,%1,%2,%3};" \
        : "+f"((d)[0]), "+f"((d)[1]), "+f"((d)[2]), "+f"((d)[3]) \
        : "r"((a)[0]), "r"((a)[1]), "r"((a)[2]), "r"((a)[3]), "r"(b0), "r"(b1))

__device__ __forceinline__ unsigned long long packkey(float s, int k) {
    unsigned u = __float_as_uint(s);
    u = (u & 0x80000000u) ? ~u : (u | 0x80000000u);
    return ((unsigned long long)u << 32) | (unsigned)k;
}
__device__ __forceinline__ float unpack_score(unsigned long long key) {
    unsigned u = (unsigned)(key >> 32);
    u = (u & 0x80000000u) ? (u & 0x7FFFFFFFu) : ~u;
    return __uint_as_float(u);
}

// ---------------------------------------------------------------------------
// 1) codebook row norms (unchanged from passing round)
// ---------------------------------------------------------------------------
__global__ void enorm_kernel(const float* __restrict__ cb) {
    int k = blockIdx.x * blockDim.x + threadIdx.x;
    if (k < K_CODES) {
        const float4* row = reinterpret_cast<const float4*>(cb + (size_t)k * C_DIM);
        float s = 0.f;
        #pragma unroll
        for (int i = 0; i < C_DIM / 4; i++) {
            float4 v = row[i];
            s += v.x*v.x + v.y*v.y + v.z*v.z + v.w*v.w;
        }
        g_enorm[k] = s;
    }
}

// 2) codebook bf16 (hi only)
__global__ void split_cb_kernel(const float* __restrict__ cb) {
    int f = blockIdx.x * blockDim.x + threadIdx.x;
    if (f < K_CODES * C_DIM) g_cbhi[f] = __float2bfloat16(cb[f]);
}

// ---------------------------------------------------------------------------
// 3) fused VQ kernel: 64 pixels/CTA x 1024 codes.
//    bf16 HMMA approx scores -> running-min + margin candidate emission ->
//    exact fp32 sequential-FMA-chain recheck (reference bit-semantics).
// ---------------------------------------------------------------------------
// SMEM layout (bytes). All wide-access strides/offsets are 16B multiples
// (XF_STRIDE was 66 floats = 264B -> misaligned float4 stores; now 68 = 272B).
#define XF_STRIDE  68              // floats  (272B/row, 16B aligned)
#define OFF_XF    0                // 256*68*4  = 69632
#define OFF_XBF   69632            // 256*144   = 36864  (72 bf16/row)
#define OFF_CB    106496           // 128*528   = 67584
#define OFF_EN    174080           // 1024 f32
#define OFF_XN    178176           // 64 f32
#define OFF_BEST  178432           // 64 u64
#define OFF_BESTE 178944           // 64 u64
#define OFF_CNT   179456           // 16
#define OFF_CAND  179472           // 3072 u32
#define SMEM_TOTAL 191760

__global__ __launch_bounds__(256, 1)
void vq_hmma_kernel(const float* __restrict__ x, const float* __restrict__ cb) {
    extern __shared__ char smem[];
    const uint32_t sb = smem_u32(smem);
    const int tid = threadIdx.x, wid = tid >> 5, lane = tid & 31;
    const int p0 = blockIdx.x * TNPIX;
    const int b  = p0 >> 12;
    const int hw0 = p0 & (HW - 1);

    float* xf   = reinterpret_cast<float*>(smem + OFF_XF);
    float* en_s = reinterpret_cast<float*>(smem + OFF_EN);
    float* xn_s = reinterpret_cast<float*>(smem + OFF_XN);
    unsigned long long* best  = reinterpret_cast<unsigned long long*>(smem + OFF_BEST);
    unsigned long long* beste = reinterpret_cast<unsigned long long*>(smem + OFF_BESTE);
    unsigned* cand = reinterpret_cast<unsigned*>(smem + OFF_CAND);
    int* cnt = reinterpret_cast<int*>(smem + OFF_CNT);

    if (tid == 0) *cnt = 0;
    if (tid < TNPIX) {
        best[tid]  = 0xFFFFFFFFFFFFFFFFULL;
        beste[tid] = 0xFFFFFFFFFFFFFFFFULL;
    }
    for (int i = tid; i < K_CODES; i += 256) en_s[i] = g_enorm[i];

    // ---- load x tile [256 c][64 px] fp32 + derive bf16 copy
    {
        const float* xb = x + (size_t)b * C_DIM * HW + hw0;
        #pragma unroll
        for (int it = 0; it < 16; it++) {
            int f = tid + it * 256;        // 0..4095 float4s
            int row = f >> 4, q = f & 15;  // 16 float4 per 64-px row
            float4 v = *reinterpret_cast<const float4*>(xb + (size_t)row * HW + q * 4);
            *reinterpret_cast<float4*>(&xf[row * XF_STRIDE + q * 4]) = v;
            __nv_bfloat16 b0 = __float2bfloat16(v.x), b1 = __float2bfloat16(v.y);
            __nv_bfloat16 b2 = __float2bfloat16(v.z), b3 = __float2bfloat16(v.w);
            uint32_t lo = ((uint32_t)__bfloat16_as_ushort(b1) << 16) | __bfloat16_as_ushort(b0);
            uint32_t hi = ((uint32_t)__bfloat16_as_ushort(b3) << 16) | __bfloat16_as_ushort(b2);
            uint2 pk = make_uint2(lo, hi);
            *reinterpret_cast<uint2*>(smem + OFF_XBF + row * 144 + q * 8) = pk;
        }
    }
    __syncthreads();

    // ---- pixel norms: exact reference order (square-round, then add, c ascending)
    if (tid < TNPIX) {
        float s = 0.f;
        #pragma unroll 8
        for (int c = 0; c < C_DIM; c++) {
            float v = xf[c * XF_STRIDE + tid];
            s = __fadd_rn(s, __fmul_rn(v, v));
        }
        xn_s[tid] = s;
    }
    __syncthreads();

    // warp tile: 32 codes x 32 px
    const int cblk = (wid >> 1) * 32;     // code sub-block within 128-code ktile
    const int pblk = (wid & 1) * 32;      // pixel sub-block

    for (int kt = 0; kt < 8; kt++) {
        // load cb tile: 128 codes x 256 c bf16 (rows 512B, padded stride 528B)
        {
            const uint4* src = reinterpret_cast<const uint4*>(&g_cbhi[(size_t)(kt * 128) * C_DIM]);
            #pragma unroll
            for (int it = 0; it < 16; it++) {
                int f = tid + it * 256;      // 0..4095
                int row = f >> 5, u = f & 31;
                uint4 v = src[(size_t)row * 32 + u];
                *reinterpret_cast<uint4*>(smem + OFF_CB + row * 528 + u * 16) = v;
            }
        }
        __syncthreads();

        float acc[2][4][4];
        #pragma unroll
        for (int m = 0; m < 2; m++)
            #pragma unroll
            for (int n = 0; n < 4; n++)
                #pragma unroll
                for (int j = 0; j < 4; j++) acc[m][n][j] = 0.f;

        const uint32_t a_rowsel = (uint32_t)(lane & 15);
        const uint32_t a_half   = (uint32_t)(lane >> 4);
        #pragma unroll 4
        for (int ccn = 0; ccn < 16; ccn++) {
            uint32_t a[2][4], bfr[2][4];
            #pragma unroll
            for (int m = 0; m < 2; m++) {
                uint32_t addr = sb + OFF_CB + (cblk + m * 16 + a_rowsel) * 528
                              + ccn * 32 + a_half * 16;
                LDSM_X4(a[m], addr);
            }
            #pragma unroll
            for (int nq = 0; nq < 2; nq++) {
                uint32_t addr = sb + OFF_XBF + (ccn * 16 + a_rowsel) * 144
                              + (pblk + nq * 16 + a_half * 8) * 2;
                LDSM_X4_T(bfr[nq], addr);
            }
            #pragma unroll
            for (int m = 0; m < 2; m++)
                #pragma unroll
                for (int n = 0; n < 4; n++)
                    MMA_BF16(acc[m][n], a[m], bfr[n >> 1][(n & 1) * 2], bfr[n >> 1][(n & 1) * 2 + 1]);
        }

        // ---- per-tile running-min update (warp pre-reduce, then smem atomicMin)
        unsigned long long key[4][2];
        #pragma unroll
        for (int n = 0; n < 4; n++)
            #pragma unroll
            for (int co = 0; co < 2; co++) {
                int px = pblk + n * 8 + (lane & 3) * 2 + co;
                float xn = xn_s[px];
                unsigned long long kk = 0xFFFFFFFFFFFFFFFFULL;
                #pragma unroll
                for (int m = 0; m < 2; m++)
                    #pragma unroll
                    for (int rr = 0; rr < 2; rr++) {
                        int code = kt * 128 + cblk + m * 16 + (lane >> 2) + rr * 8;
                        float s = __fsub_rn(__fadd_rn(xn, en_s[code]),
                                            __fmul_rn(2.f, acc[m][n][rr * 2 + co]));
                        unsigned long long k2 = packkey(s, code);
                        if (k2 < kk) kk = k2;
                    }
                #pragma unroll
                for (int d = 4; d < 32; d <<= 1) {
                    unsigned long long o = __shfl_xor_sync(0xFFFFFFFFu, kk, d);
                    if (o < kk) kk = o;
                }
                key[n][co] = kk;
            }
        if (lane < 4) {
            #pragma unroll
            for (int n = 0; n < 4; n++)
                #pragma unroll
                for (int co = 0; co < 2; co++)
                    atomicMin(&best[pblk + n * 8 + lane * 2 + co], key[n][co]);
        }
        __syncthreads();

        // ---- candidate emission vs running min (superset of final candidates)
        #pragma unroll
        for (int n = 0; n < 4; n++)
            #pragma unroll
            for (int co = 0; co < 2; co++) {
                int px = pblk + n * 8 + (lane & 3) * 2 + co;
                float thr = unpack_score(best[px]) + MARGIN;
                float xn = xn_s[px];
                #pragma unroll
                for (int m = 0; m < 2; m++)
                    #pragma unroll
                    for (int rr = 0; rr < 2; rr++) {
                        int code = kt * 128 + cblk + m * 16 + (lane >> 2) + rr * 8;
                        float s = __fsub_rn(__fadd_rn(xn, en_s[code]),
                                            __fmul_rn(2.f, acc[m][n][rr * 2 + co]));
                        if (s <= thr) {
                            int pos = atomicAdd(cnt, 1);
                            if (pos < CAND_CAP)
                                cand[pos] = ((unsigned)px << 10) | (unsigned)code;
                        }
                    }
            }
        __syncthreads();   // before next tile's cb overwrite / best updates
    }

    // ---- exact recheck: sequential fp32 FMA chain, c ascending (reference order)
    int n = *cnt; if (n > CAND_CAP) n = CAND_CAP;
    for (int t = tid; t < n; t += 256) {
        unsigned e = cand[t];
        int px = (int)(e >> 10);
        int k  = (int)(e & 1023u);
        const float* ck = cb + (size_t)k * C_DIM;
        float dot = 0.f;
        #pragma unroll 8
        for (int c = 0; c < C_DIM; c++)
            dot = __fmaf_rn(ck[c], xf[c * XF_STRIDE + px], dot);
        float s = __fsub_rn(__fadd_rn(xn_s[px], en_s[k]), __fmul_rn(2.f, dot));
        atomicMin(&beste[px], packkey(s, k));
    }
    __syncthreads();
    if (tid < TNPIX) g_idx[p0 + tid] = (int)(beste[tid] & 0xFFFFFFFFu);
}

// ---------------------------------------------------------------------------
// 4) outputs (unchanged from passing round)
// ---------------------------------------------------------------------------
__global__ void gather_kernel(const float* __restrict__ cb, float* __restrict__ q) {
    long long o = (long long)blockIdx.x * blockDim.x + threadIdx.x;
    if (o >= (long long)QN) return;
    int hw = (int)(o & (HW - 1));
    long long t = o >> 12;
    int c = (int)(t & (C_DIM - 1));
    int b = (int)(t >> 8);
    int k = g_idx[b * HW + hw];
    q[o] = __ldg(cb + (size_t)k * C_DIM + c);
}
__global__ void idxf_kernel(float* __restrict__ out) {
    int n = blockIdx.x * blockDim.x + threadIdx.x;
    if (n < NPIX) out[n] = (float)g_idx[n];
}
__global__ void idxi_kernel(int* __restrict__ out) {
    int n = blockIdx.x * blockDim.x + threadIdx.x;
    if (n < NPIX) out[n] = g_idx[n];
}

// ---------------------------------------------------------------------------
extern "C" void kernel_launch(void* const* d_in, const int* in_sizes, int n_in,
                              void* d_out, int out_size) {
    const float* x  = (const float*)d_in[0];   // (32,256,64,64) f32
    const float* cb = (const float*)d_in[1];   // (1024,256) f32

    cudaFuncSetAttribute(vq_hmma_kernel,
                         cudaFuncAttributeMaxDynamicSharedMemorySize, SMEM_TOTAL);

    enorm_kernel<<<(K_CODES + 255) / 256, 256>>>(cb);
    split_cb_kernel<<<(K_CODES * C_DIM) / 256, 256>>>(cb);
    vq_hmma_kernel<<<NPIX / TNPIX, 256, SMEM_TOTAL>>>(x, cb);

    if (out_size >= NPIX + QN) {
        idxf_kernel<<<NPIX / 256, 256>>>((float*)d_out);
        gather_kernel<<<QN / 256, 256>>>(cb, (float*)d_out + NPIX);
    } else if (out_size >= QN) {
        gather_kernel<<<QN / 256, 256>>>(cb, (float*)d_out);
    } else if (out_size >= NPIX) {
        idxi_kernel<<<NPIX / 256, 256>>>((int*)d_out);
    }
}

// round 7
// speedup vs baseline: 1.4903x; 1.2421x over previous
#include <cuda_runtime.h>
#include <cuda_bf16.h>
#include <cstdint>

// ---------------------------------------------------------------------------
// Problem constants
// ---------------------------------------------------------------------------
#define K_CODES 1024
#define C_DIM   256
#define HW      4096
#define BATCH   32
#define NPIX    (BATCH*HW)          // 131072
#define QN      (BATCH*C_DIM*HW)    // 8388608

#define TNPIX   64                  // pixels per CTA
#define MARGIN  4e-3f
#define CAND_CAP 3072

// Scratch (device globals; no cudaMalloc allowed)
__device__ float g_enorm[K_CODES];
__device__ int   g_idx[NPIX];
__device__ __nv_bfloat16 g_cbhi[K_CODES * C_DIM];

// ---------------------------------------------------------------------------
// PTX helpers — plain features only (compute_103-safe)
// ---------------------------------------------------------------------------
__device__ __forceinline__ uint32_t smem_u32(const void* p) {
    uint32_t a;
    asm("{ .reg .u64 t; cvta.to.shared.u64 t, %1; cvt.u32.u64 %0, t; }" : "=r"(a) : "l"(p));
    return a;
}
#define LDSM_X4(r, a) \
    asm volatile("ldmatrix.sync.aligned.m8n8.x4.shared.b16 {%0,%1,%2,%3}, [%4];" \
        : "=r"((r)[0]), "=r"((r)[1]), "=r"((r)[2]), "=r"((r)[3]) : "r"(a))
#define LDSM_X4_T(r, a) \
    asm volatile("ldmatrix.sync.aligned.m8n8.x4.trans.shared.b16 {%0,%1,%2,%3}, [%4];" \
        : "=r"((r)[0]), "=r"((r)[1]), "=r"((r)[2]), "=r"((r)[3]) : "r"(a))
#define MMA_BF16(d, a, b0, b1) \
    asm volatile("mma.sync.aligned.m16n8k16.row.col.f32.bf16.bf16.f32 " \
        "{%0,%1,%2,%3}, {%4,%5,%6,%7}, {%8,%9}, {%0,%1,%2,%3};" \
        : "+f"((d)[0]), "+f"((d)[1]), "+f"((d)[2]), "+f"((d)[3]) \
        : "r"((a)[0]), "r"((a)[1]), "r"((a)[2]), "r"((a)[3]), "r"(b0), "r"(b1))
#define CP_ASYNC16(dst, src) \
    asm volatile("cp.async.cg.shared.global [%0], [%1], 16;" :: "r"(dst), "l"(src))
#define CP_COMMIT() asm volatile("cp.async.commit_group;")
#define CP_WAIT(n)  asm volatile("cp.async.wait_group %0;" :: "n"(n))

__device__ __forceinline__ unsigned long long packkey(float s, int k) {
    unsigned u = __float_as_uint(s);
    u = (u & 0x80000000u) ? ~u : (u | 0x80000000u);
    return ((unsigned long long)u << 32) | (unsigned)k;
}
__device__ __forceinline__ float unpack_score(unsigned long long key) {
    unsigned u = (unsigned)(key >> 32);
    u = (u & 0x80000000u) ? (u & 0x7FFFFFFFu) : ~u;
    return __uint_as_float(u);
}

// ---------------------------------------------------------------------------
// 1) codebook row norms / bf16 copy (unchanged)
// ---------------------------------------------------------------------------
__global__ void enorm_kernel(const float* __restrict__ cb) {
    int k = blockIdx.x * blockDim.x + threadIdx.x;
    if (k < K_CODES) {
        const float4* row = reinterpret_cast<const float4*>(cb + (size_t)k * C_DIM);
        float s = 0.f;
        #pragma unroll
        for (int i = 0; i < C_DIM / 4; i++) {
            float4 v = row[i];
            s += v.x*v.x + v.y*v.y + v.z*v.z + v.w*v.w;
        }
        g_enorm[k] = s;
    }
}
__global__ void split_cb_kernel(const float* __restrict__ cb) {
    int f = blockIdx.x * blockDim.x + threadIdx.x;
    if (f < K_CODES * C_DIM) g_cbhi[f] = __float2bfloat16(cb[f]);
}

// ---------------------------------------------------------------------------
// 2) fused VQ kernel: 64 px/CTA x 1024 codes.
//    64x64 warp tiles (16 MAC/smem-byte), cp.async double-buffered cb chunks,
//    2 epilogues; exact fp32 sequential-FMA recheck (verified bit-semantics).
// ---------------------------------------------------------------------------
#define XF_STRIDE  68              // floats (272B/row, 16B aligned)
#define CB_ROW     80              // bytes per 32-c cb chunk row (bank-phase spread)
#define CB_BUF     40960           // 512 rows * 80B
#define OFF_XF    0                // 69632
#define OFF_XBF   69632            // 256*144 = 36864
#define OFF_CB    106496           // 2*40960 = 81920
#define OFF_EN    188416           // 4096
#define OFF_XN    192512           // 256
#define OFF_BEST  192768           // 512
#define OFF_BESTE 193280           // 512
#define OFF_CNT   193792           // 16
#define OFF_CAND  193808           // 12288
#define SMEM_TOTAL 206096

__global__ __launch_bounds__(256, 1)
void vq_hmma_kernel(const float* __restrict__ x, const float* __restrict__ cb) {
    extern __shared__ char smem[];
    const uint32_t sb = smem_u32(smem);
    const int tid = threadIdx.x, wid = tid >> 5, lane = tid & 31;
    const int p0 = blockIdx.x * TNPIX;
    const int b  = p0 >> 12;
    const int hw0 = p0 & (HW - 1);

    float* xf   = reinterpret_cast<float*>(smem + OFF_XF);
    float* en_s = reinterpret_cast<float*>(smem + OFF_EN);
    float* xn_s = reinterpret_cast<float*>(smem + OFF_XN);
    unsigned long long* best  = reinterpret_cast<unsigned long long*>(smem + OFF_BEST);
    unsigned long long* beste = reinterpret_cast<unsigned long long*>(smem + OFF_BESTE);
    unsigned* cand = reinterpret_cast<unsigned*>(smem + OFF_CAND);
    int* cnt = reinterpret_cast<int*>(smem + OFF_CNT);

    if (tid == 0) *cnt = 0;
    if (tid < TNPIX) {
        best[tid]  = 0xFFFFFFFFFFFFFFFFULL;
        beste[tid] = 0xFFFFFFFFFFFFFFFFULL;
    }
    for (int i = tid; i < K_CODES; i += 256) en_s[i] = g_enorm[i];

    const char* cbbytes = reinterpret_cast<const char*>(g_cbhi);

    // kick off cb chunk 0 load (512 codes x 32 c) while we load the x tile
    {
        uint32_t dbase = sb + OFF_CB;
        #pragma unroll
        for (int i = 0; i < 8; i++) {
            int f = tid + i * 256;            // 0..2047
            int row = f >> 2, seg = f & 3;
            CP_ASYNC16(dbase + row * CB_ROW + seg * 16,
                       cbbytes + (size_t)row * 512 + seg * 16);
        }
        CP_COMMIT();
    }

    // ---- x tile [256 c][64 px]: fp32 + bf16 copies
    {
        const float* xb = x + (size_t)b * C_DIM * HW + hw0;
        #pragma unroll
        for (int it = 0; it < 16; it++) {
            int f = tid + it * 256;
            int row = f >> 4, q = f & 15;
            float4 v = *reinterpret_cast<const float4*>(xb + (size_t)row * HW + q * 4);
            *reinterpret_cast<float4*>(&xf[row * XF_STRIDE + q * 4]) = v;
            __nv_bfloat16 b0 = __float2bfloat16(v.x), b1 = __float2bfloat16(v.y);
            __nv_bfloat16 b2 = __float2bfloat16(v.z), b3 = __float2bfloat16(v.w);
            uint32_t lo = ((uint32_t)__bfloat16_as_ushort(b1) << 16) | __bfloat16_as_ushort(b0);
            uint32_t hi = ((uint32_t)__bfloat16_as_ushort(b3) << 16) | __bfloat16_as_ushort(b2);
            *reinterpret_cast<uint2*>(smem + OFF_XBF + row * 144 + q * 8) = make_uint2(lo, hi);
        }
    }
    __syncthreads();

    // ---- pixel norms: exact reference order
    if (tid < TNPIX) {
        float s = 0.f;
        #pragma unroll 8
        for (int c = 0; c < C_DIM; c++) {
            float v = xf[c * XF_STRIDE + tid];
            s = __fadd_rn(s, __fmul_rn(v, v));
        }
        xn_s[tid] = s;
    }
    __syncthreads();

    const uint32_t a_rowsel = (uint32_t)(lane & 15);
    const uint32_t a_half   = (uint32_t)(lane >> 4);

    float acc[4][8][4];

    // ---- 16 chunks: kt = g>>3 (512-code block), cc = g&7 (32-c slice)
    for (int g = 0; g < 16; g++) {
        const int buf = g & 1;
        if (g < 16 - 1) {
            // prefetch chunk g+1 into other buffer
            int gn = g + 1;
            int ktn = gn >> 3, ccn_ = gn & 7;
            uint32_t dbase = sb + OFF_CB + (buf ^ 1) * CB_BUF;
            const char* srcb = cbbytes + (size_t)(ktn * 512) * 512 + ccn_ * 64;
            #pragma unroll
            for (int i = 0; i < 8; i++) {
                int f = tid + i * 256;
                int row = f >> 2, seg = f & 3;
                CP_ASYNC16(dbase + row * CB_ROW + seg * 16,
                           srcb + (size_t)row * 512 + seg * 16);
            }
            CP_COMMIT();
            CP_WAIT(1);
        } else {
            CP_WAIT(0);
        }
        __syncthreads();   // chunk g visible to all threads

        if ((g & 7) == 0) {
            #pragma unroll
            for (int m = 0; m < 4; m++)
                #pragma unroll
                for (int n = 0; n < 8; n++)
                    #pragma unroll
                    for (int j = 0; j < 4; j++) acc[m][n][j] = 0.f;
        }

        const uint32_t abase = sb + OFF_CB + buf * CB_BUF;
        const int cc = g & 7;
        #pragma unroll
        for (int ccn = 0; ccn < 2; ccn++) {
            uint32_t a[4][4], bfr[4][4];
            #pragma unroll
            for (int m = 0; m < 4; m++) {
                uint32_t addr = abase + (wid * 64 + m * 16 + a_rowsel) * CB_ROW
                              + ccn * 32 + a_half * 16;
                LDSM_X4(a[m], addr);
            }
            #pragma unroll
            for (int np = 0; np < 4; np++) {
                uint32_t addr = sb + OFF_XBF + (cc * 32 + ccn * 16 + a_rowsel) * 144
                              + (np * 16 + a_half * 8) * 2;
                LDSM_X4_T(bfr[np], addr);
            }
            #pragma unroll
            for (int m = 0; m < 4; m++)
                #pragma unroll
                for (int n = 0; n < 8; n++)
                    MMA_BF16(acc[m][n], a[m], bfr[n >> 1][(n & 1) * 2], bfr[n >> 1][(n & 1) * 2 + 1]);
        }

        if ((g & 7) == 7) {
            const int kt = g >> 3;
            // ---- running-min update (thread min -> lane-group shfl -> smem atomicMin)
            #pragma unroll
            for (int n = 0; n < 8; n++)
                #pragma unroll
                for (int co = 0; co < 2; co++) {
                    int px = n * 8 + (lane & 3) * 2 + co;
                    float xn = xn_s[px];
                    unsigned long long kk = 0xFFFFFFFFFFFFFFFFULL;
                    #pragma unroll
                    for (int m = 0; m < 4; m++)
                        #pragma unroll
                        for (int rr = 0; rr < 2; rr++) {
                            int code = kt * 512 + wid * 64 + m * 16 + (lane >> 2) + rr * 8;
                            float s = __fsub_rn(__fadd_rn(xn, en_s[code]),
                                                __fmul_rn(2.f, acc[m][n][rr * 2 + co]));
                            unsigned long long k2 = packkey(s, code);
                            if (k2 < kk) kk = k2;
                        }
                    #pragma unroll
                    for (int d = 4; d < 32; d <<= 1) {
                        unsigned long long o = __shfl_xor_sync(0xFFFFFFFFu, kk, d);
                        if (o < kk) kk = o;
                    }
                    if ((lane >> 2) == 0) atomicMin(&best[px], kk);
                }
            __syncthreads();
            // ---- candidate emission vs running min (superset of final winners)
            #pragma unroll
            for (int n = 0; n < 8; n++)
                #pragma unroll
                for (int co = 0; co < 2; co++) {
                    int px = n * 8 + (lane & 3) * 2 + co;
                    float thr = unpack_score(best[px]) + MARGIN;
                    float xn = xn_s[px];
                    #pragma unroll
                    for (int m = 0; m < 4; m++)
                        #pragma unroll
                        for (int rr = 0; rr < 2; rr++) {
                            int code = kt * 512 + wid * 64 + m * 16 + (lane >> 2) + rr * 8;
                            float s = __fsub_rn(__fadd_rn(xn, en_s[code]),
                                                __fmul_rn(2.f, acc[m][n][rr * 2 + co]));
                            if (s <= thr) {
                                int pos = atomicAdd(cnt, 1);
                                if (pos < CAND_CAP)
                                    cand[pos] = ((unsigned)px << 10) | (unsigned)code;
                            }
                        }
                }
        }
        __syncthreads();   // compute done before this buffer is reloaded
    }

    // ---- exact recheck: sequential fp32 FMA chain, c ascending (reference order)
    int n = *cnt; if (n > CAND_CAP) n = CAND_CAP;
    for (int t = tid; t < n; t += 256) {
        unsigned e = cand[t];
        int px = (int)(e >> 10);
        int k  = (int)(e & 1023u);
        const float* ck = cb + (size_t)k * C_DIM;
        float dot = 0.f;
        #pragma unroll 8
        for (int c = 0; c < C_DIM; c++)
            dot = __fmaf_rn(ck[c], xf[c * XF_STRIDE + px], dot);
        float s = __fsub_rn(__fadd_rn(xn_s[px], en_s[k]), __fmul_rn(2.f, dot));
        atomicMin(&beste[px], packkey(s, k));
    }
    __syncthreads();
    if (tid < TNPIX) g_idx[p0 + tid] = (int)(beste[tid] & 0xFFFFFFFFu);
}

// ---------------------------------------------------------------------------
// 3) outputs (unchanged)
// ---------------------------------------------------------------------------
__global__ void gather_kernel(const float* __restrict__ cb, float* __restrict__ q) {
    long long o = (long long)blockIdx.x * blockDim.x + threadIdx.x;
    if (o >= (long long)QN) return;
    int hw = (int)(o & (HW - 1));
    long long t = o >> 12;
    int c = (int)(t & (C_DIM - 1));
    int b = (int)(t >> 8);
    int k = g_idx[b * HW + hw];
    q[o] = __ldg(cb + (size_t)k * C_DIM + c);
}
__global__ void idxf_kernel(float* __restrict__ out) {
    int n = blockIdx.x * blockDim.x + threadIdx.x;
    if (n < NPIX) out[n] = (float)g_idx[n];
}
__global__ void idxi_kernel(int* __restrict__ out) {
    int n = blockIdx.x * blockDim.x + threadIdx.x;
    if (n < NPIX) out[n] = g_idx[n];
}

// ---------------------------------------------------------------------------
extern "C" void kernel_launch(void* const* d_in, const int* in_sizes, int n_in,
                              void* d_out, int out_size) {
    const float* x  = (const float*)d_in[0];   // (32,256,64,64) f32
    const float* cb = (const float*)d_in[1];   // (1024,256) f32

    cudaFuncSetAttribute(vq_hmma_kernel,
                         cudaFuncAttributeMaxDynamicSharedMemorySize, SMEM_TOTAL);

    enorm_kernel<<<(K_CODES + 255) / 256, 256>>>(cb);
    split_cb_kernel<<<(K_CODES * C_DIM) / 256, 256>>>(cb);
    vq_hmma_kernel<<<NPIX / TNPIX, 256, SMEM_TOTAL>>>(x, cb);

    if (out_size >= NPIX + QN) {
        idxf_kernel<<<NPIX / 256, 256>>>((float*)d_out);
        gather_kernel<<<QN / 256, 256>>>(cb, (float*)d_out + NPIX);
    } else if (out_size >= QN) {
        gather_kernel<<<QN / 256, 256>>>(cb, (float*)d_out);
    } else if (out_size >= NPIX) {
        idxi_kernel<<<NPIX / 256, 256>>>((int*)d_out);
    }
}